// round 2
// baseline (speedup 1.0000x reference)
#include <cuda_runtime.h>
#include <math.h>

#define Bv   8
#define Cv   128
#define HWv  262144
#define Kv   64
#define BKv  512
#define NNEG 7
#define Pv   4096
#define INV_TAU (1.0f / 0.07f)

// ---- scratch (static device globals; no allocation) ----
__device__ float g_pool_inv[Pv];
__device__ float g_q[BKv * Cv];        // normalized query vectors
__device__ float g_partmax[BKv * 64];  // per (query, pool-tile) partial max
__device__ float g_loss[BKv];

// ---------------------------------------------------------------------------
// A: inverse L2 norm of each pool row (one warp per row)
// ---------------------------------------------------------------------------
__global__ void pool_norm_kernel(const float* __restrict__ pool) {
    int warp = threadIdx.x >> 5, lane = threadIdx.x & 31;
    int row = blockIdx.x * 8 + warp;
    float4 v = *reinterpret_cast<const float4*>(pool + (size_t)row * Cv + lane * 4);
    float ss = v.x * v.x + v.y * v.y + v.z * v.z + v.w * v.w;
#pragma unroll
    for (int o = 16; o; o >>= 1) ss += __shfl_xor_sync(0xffffffffu, ss, o);
    if (lane == 0) g_pool_inv[row] = 1.0f / fmaxf(sqrtf(ss), 1e-12f);
}

// ---------------------------------------------------------------------------
// B: gather sampled query pixels (strided across C) and L2-normalize
// one block (128 threads) per (b,k)
// ---------------------------------------------------------------------------
__global__ void q_gather_kernel(const float* __restrict__ feat,
                                const int* __restrict__ qidx) {
    int q = blockIdx.x;
    int b = q >> 6;            // K = 64
    int c = threadIdx.x;
    int idx = qidx[q];
    float v = feat[(size_t)b * ((size_t)Cv * HWv) + (size_t)c * HWv + (size_t)idx];
    __shared__ float red[4];
    float ss = v * v;
#pragma unroll
    for (int o = 16; o; o >>= 1) ss += __shfl_xor_sync(0xffffffffu, ss, o);
    if ((c & 31) == 0) red[c >> 5] = ss;
    __syncthreads();
    float tot = red[0] + red[1] + red[2] + red[3];
    float inv = 1.0f / fmaxf(sqrtf(tot), 1e-12f);
    g_q[q * Cv + c] = v * inv;
}

// ---------------------------------------------------------------------------
// C: sim = Qn[512,128] x PoolT[128,4096], track max over each 64-col pool tile
// 64x64 block tile, 4x4 register tile, K split in two 64-wide stages.
// grid = (64 pool tiles, 8 q tiles), 256 threads.
// ---------------------------------------------------------------------------
__global__ void sim_kernel(const float* __restrict__ pool) {
    __shared__ float sq[64][65];
    __shared__ float sp[64][65];
    int tid = threadIdx.x;
    int tx = tid & 15, ty = tid >> 4;
    int qbase = blockIdx.y << 6;
    int pbase = blockIdx.x << 6;

    float acc[4][4];
#pragma unroll
    for (int i = 0; i < 4; ++i)
#pragma unroll
        for (int j = 0; j < 4; ++j) acc[i][j] = 0.0f;

#pragma unroll
    for (int s = 0; s < 2; ++s) {
        __syncthreads();
#pragma unroll
        for (int u = 0; u < 4; ++u) {
            int f = tid + u * 256;          // 1024 float4 slots per tile
            int row = f >> 4;
            int c4 = (f & 15) << 2;
            float4 a = *reinterpret_cast<const float4*>(
                &g_q[(qbase + row) * Cv + s * 64 + c4]);
            sq[row][c4 + 0] = a.x; sq[row][c4 + 1] = a.y;
            sq[row][c4 + 2] = a.z; sq[row][c4 + 3] = a.w;
            float4 b = *reinterpret_cast<const float4*>(
                &pool[(size_t)(pbase + row) * Cv + s * 64 + c4]);
            sp[row][c4 + 0] = b.x; sp[row][c4 + 1] = b.y;
            sp[row][c4 + 2] = b.z; sp[row][c4 + 3] = b.w;
        }
        __syncthreads();
#pragma unroll
        for (int k = 0; k < 64; ++k) {
            float a0 = sq[ty * 4 + 0][k];
            float a1 = sq[ty * 4 + 1][k];
            float a2 = sq[ty * 4 + 2][k];
            float a3 = sq[ty * 4 + 3][k];
            float b0 = sp[tx * 4 + 0][k];
            float b1 = sp[tx * 4 + 1][k];
            float b2 = sp[tx * 4 + 2][k];
            float b3 = sp[tx * 4 + 3][k];
            acc[0][0] += a0 * b0; acc[0][1] += a0 * b1; acc[0][2] += a0 * b2; acc[0][3] += a0 * b3;
            acc[1][0] += a1 * b0; acc[1][1] += a1 * b1; acc[1][2] += a1 * b2; acc[1][3] += a1 * b3;
            acc[2][0] += a2 * b0; acc[2][1] += a2 * b1; acc[2][2] += a2 * b2; acc[2][3] += a2 * b3;
            acc[3][0] += a3 * b0; acc[3][1] += a3 * b1; acc[3][2] += a3 * b2; acc[3][3] += a3 * b3;
        }
    }

    float inv[4];
#pragma unroll
    for (int j = 0; j < 4; ++j) inv[j] = g_pool_inv[pbase + tx * 4 + j];

    float m[4];
#pragma unroll
    for (int i = 0; i < 4; ++i) {
        float best = -1e30f;
#pragma unroll
        for (int j = 0; j < 4; ++j) best = fmaxf(best, acc[i][j] * inv[j]);
        m[i] = best;
    }
    // reduce across the 16 tx lanes (stays inside each half-warp)
#pragma unroll
    for (int o = 8; o; o >>= 1)
#pragma unroll
        for (int i = 0; i < 4; ++i)
            m[i] = fmaxf(m[i], __shfl_xor_sync(0xffffffffu, m[i], o));

    if (tx == 0) {
#pragma unroll
        for (int i = 0; i < 4; ++i)
            g_partmax[(qbase + ty * 4 + i) * 64 + blockIdx.x] = m[i];
    }
}

// ---------------------------------------------------------------------------
// D: per-query: combine partial maxes (positive logit), 7 negatives, softmax CE
// one warp per query, 8 warps per block
// ---------------------------------------------------------------------------
__global__ void finalize_kernel(const float* __restrict__ negs) {
    int warp = threadIdx.x >> 5, lane = threadIdx.x & 31;
    int q = blockIdx.x * 8 + warp;

    float pm = fmaxf(g_partmax[q * 64 + lane], g_partmax[q * 64 + 32 + lane]);
#pragma unroll
    for (int o = 16; o; o >>= 1) pm = fmaxf(pm, __shfl_xor_sync(0xffffffffu, pm, o));

    float4 qv = *reinterpret_cast<const float4*>(&g_q[q * Cv + lane * 4]);

    float logits[8];
    logits[0] = pm * INV_TAU;
#pragma unroll
    for (int n = 0; n < NNEG; ++n) {
        float4 nv = *reinterpret_cast<const float4*>(
            &negs[((size_t)q * NNEG + n) * Cv + lane * 4]);
        float d  = nv.x * qv.x + nv.y * qv.y + nv.z * qv.z + nv.w * qv.w;
        float s2 = nv.x * nv.x + nv.y * nv.y + nv.z * nv.z + nv.w * nv.w;
#pragma unroll
        for (int o = 16; o; o >>= 1) {
            d  += __shfl_xor_sync(0xffffffffu, d, o);
            s2 += __shfl_xor_sync(0xffffffffu, s2, o);
        }
        logits[1 + n] = d / fmaxf(sqrtf(s2), 1e-12f) * INV_TAU;
    }

    float mx = logits[0];
#pragma unroll
    for (int i = 1; i < 8; ++i) mx = fmaxf(mx, logits[i]);
    float se = 0.0f;
#pragma unroll
    for (int i = 0; i < 8; ++i) se += expf(logits[i] - mx);
    if (lane == 0) g_loss[q] = -(logits[0] - mx - logf(se));
}

// ---------------------------------------------------------------------------
// E: deterministic mean over the 512 per-query losses
// ---------------------------------------------------------------------------
__global__ void reduce_kernel(float* __restrict__ out) {
    __shared__ float red[256];
    int t = threadIdx.x;
    red[t] = g_loss[t] + g_loss[t + 256];
    __syncthreads();
    for (int s = 128; s; s >>= 1) {
        if (t < s) red[t] += red[t + s];
        __syncthreads();
    }
    if (t == 0) out[0] = red[0] * (1.0f / (float)BKv);
}

// ---------------------------------------------------------------------------
extern "C" void kernel_launch(void* const* d_in, const int* in_sizes, int n_in,
                              void* d_out, int out_size) {
    const float* feat = (const float*)d_in[0];   // [B, C, H, W]
    const float* pool = (const float*)d_in[1];   // [P, C]
    const float* negs = (const float*)d_in[2];   // [B, K, N, C]
    const int*   qidx = (const int*)d_in[3];     // [B, K]
    float* out = (float*)d_out;

    pool_norm_kernel<<<Pv / 8, 256>>>(pool);
    q_gather_kernel<<<BKv, 128>>>(feat, qidx);
    sim_kernel<<<dim3(64, 8), 256>>>(pool);
    finalize_kernel<<<BKv / 8, 256>>>(negs);
    reduce_kernel<<<1, 256>>>(out);
}

// round 4
// speedup vs baseline: 1.1592x; 1.1592x over previous
#include <cuda_runtime.h>
#include <math.h>

#define Cv   128
#define HWv  262144
#define BKv  512
#define NNEG 7
#define Pv   4096
#define INV_TAU (1.0f / 0.07f)

// ---- scratch ----
__device__ float g_pool_inv[Pv];
__device__ float g_q[BKv * Cv];
__device__ float g_partmax[BKv * 32];   // 32 pool tiles of 128 cols
__device__ float g_loss[BKv];

// ---- f32x2 packed helpers (Blackwell FFMA2) ----
__device__ __forceinline__ unsigned long long pk2(float x, float y) {
    unsigned long long r;
    asm("mov.b64 %0,{%1,%2};" : "=l"(r) : "f"(x), "f"(y));
    return r;
}
__device__ __forceinline__ void upk2(unsigned long long v, float& x, float& y) {
    asm("mov.b64 {%0,%1},%2;" : "=f"(x), "=f"(y) : "l"(v));
}
__device__ __forceinline__ void ffma2(unsigned long long& d,
                                      unsigned long long a, unsigned long long b) {
    asm("fma.rn.f32x2 %0,%1,%2,%0;" : "+l"(d) : "l"(a), "l"(b));
}

// ---------------------------------------------------------------------------
// A+B fused: blocks 0..511 = pool inverse norms, blocks 512..1023 = q gather
// (barrier is uniform within gather blocks)
// ---------------------------------------------------------------------------
__global__ void prep_kernel(const float* __restrict__ pool,
                            const float* __restrict__ feat,
                            const int* __restrict__ qidx) {
    int bid = blockIdx.x;
    if (bid < 512) {
        int warp = threadIdx.x >> 5, lane = threadIdx.x & 31;
        int row = bid * 8 + warp;
        float4 v = *reinterpret_cast<const float4*>(pool + (size_t)row * Cv + lane * 4);
        float ss = v.x * v.x + v.y * v.y + v.z * v.z + v.w * v.w;
#pragma unroll
        for (int o = 16; o; o >>= 1) ss += __shfl_xor_sync(0xffffffffu, ss, o);
        if (lane == 0) g_pool_inv[row] = 1.0f / fmaxf(sqrtf(ss), 1e-12f);
    } else {
        int q = bid - 512;
        int c = threadIdx.x;
        __shared__ float red[4];
        float v = 0.0f;
        if (c < 128) {
            int b = q >> 6;
            int idx = qidx[q];
            v = feat[(size_t)b * ((size_t)Cv * HWv) + (size_t)c * HWv + (size_t)idx];
            float ss = v * v;
#pragma unroll
            for (int o = 16; o; o >>= 1) ss += __shfl_xor_sync(0xffffffffu, ss, o);
            if ((c & 31) == 0) red[c >> 5] = ss;
        }
        __syncthreads();
        if (c < 128) {
            float tot = red[0] + red[1] + red[2] + red[3];
            float inv = 1.0f / fmaxf(sqrtf(tot), 1e-12f);
            g_q[q * Cv + c] = v * inv;
        }
    }
}

// ---------------------------------------------------------------------------
// C: sim max.  Block tile 64q x 128p, thread tile 4x8 via packed f32x2 FMA.
// grid = (32 p-tiles, 8 q-tiles), 256 threads.
// Dynamic smem: sq[64][65] + sp[128][65] = 12480 floats = 49920 B.
// ---------------------------------------------------------------------------
#define SQ_S 65
#define SP_S 65
#define SIM_SMEM_BYTES ((64 * SQ_S + 128 * SP_S) * 4)

__global__ void sim_kernel(const float* __restrict__ pool) {
    extern __shared__ float smem[];
    float* sq = smem;                 // [64][SQ_S]
    float* sp = smem + 64 * SQ_S;     // [128][SP_S]

    int tid = threadIdx.x;
    int tx = tid & 15;            // pool-col group (cols tx + 16j)
    int ty = tid >> 4;            // q-row group   (rows ty + 16i)
    int qbase = blockIdx.y << 6;
    int pbase = blockIdx.x << 7;

    unsigned long long acc[4][4];
#pragma unroll
    for (int i = 0; i < 4; ++i)
#pragma unroll
        for (int jp = 0; jp < 4; ++jp) acc[i][jp] = 0ULL;

#pragma unroll
    for (int s = 0; s < 2; ++s) {
        __syncthreads();
        // q tile: 64 rows x 64 ch, coalesced float4 loads
#pragma unroll
        for (int u = 0; u < 4; ++u) {
            int f = tid + u * 256;
            int row = f >> 4, c4 = (f & 15) << 2;
            float4 a = *reinterpret_cast<const float4*>(
                &g_q[(qbase + row) * Cv + s * 64 + c4]);
            float* d = &sq[row * SQ_S + c4];
            d[0] = a.x; d[1] = a.y; d[2] = a.z; d[3] = a.w;
        }
        // pool tile: 128 rows x 64 ch
#pragma unroll
        for (int u = 0; u < 8; ++u) {
            int f = tid + u * 256;
            int row = f >> 4, c4 = (f & 15) << 2;
            float4 b = *reinterpret_cast<const float4*>(
                &pool[(size_t)(pbase + row) * Cv + s * 64 + c4]);
            float* d = &sp[row * SP_S + c4];
            d[0] = b.x; d[1] = b.y; d[2] = b.z; d[3] = b.w;
        }
        __syncthreads();

#pragma unroll 8
        for (int k = 0; k < 64; ++k) {
            float a0 = sq[(ty +  0) * SQ_S + k];
            float a1 = sq[(ty + 16) * SQ_S + k];
            float a2 = sq[(ty + 32) * SQ_S + k];
            float a3 = sq[(ty + 48) * SQ_S + k];
            float b0 = sp[(tx +   0) * SP_S + k];
            float b1 = sp[(tx +  16) * SP_S + k];
            float b2 = sp[(tx +  32) * SP_S + k];
            float b3 = sp[(tx +  48) * SP_S + k];
            float b4 = sp[(tx +  64) * SP_S + k];
            float b5 = sp[(tx +  80) * SP_S + k];
            float b6 = sp[(tx +  96) * SP_S + k];
            float b7 = sp[(tx + 112) * SP_S + k];
            unsigned long long aa0 = pk2(a0, a0);
            unsigned long long aa1 = pk2(a1, a1);
            unsigned long long aa2 = pk2(a2, a2);
            unsigned long long aa3 = pk2(a3, a3);
            unsigned long long bb0 = pk2(b0, b1);
            unsigned long long bb1 = pk2(b2, b3);
            unsigned long long bb2 = pk2(b4, b5);
            unsigned long long bb3 = pk2(b6, b7);
            ffma2(acc[0][0], aa0, bb0); ffma2(acc[0][1], aa0, bb1);
            ffma2(acc[0][2], aa0, bb2); ffma2(acc[0][3], aa0, bb3);
            ffma2(acc[1][0], aa1, bb0); ffma2(acc[1][1], aa1, bb1);
            ffma2(acc[1][2], aa1, bb2); ffma2(acc[1][3], aa1, bb3);
            ffma2(acc[2][0], aa2, bb0); ffma2(acc[2][1], aa2, bb1);
            ffma2(acc[2][2], aa2, bb2); ffma2(acc[2][3], aa2, bb3);
            ffma2(acc[3][0], aa3, bb0); ffma2(acc[3][1], aa3, bb1);
            ffma2(acc[3][2], aa3, bb2); ffma2(acc[3][3], aa3, bb3);
        }
    }

    float inv[8];
#pragma unroll
    for (int j = 0; j < 8; ++j) inv[j] = g_pool_inv[pbase + tx + 16 * j];

    float m[4];
#pragma unroll
    for (int i = 0; i < 4; ++i) {
        float best = -1e30f;
#pragma unroll
        for (int jp = 0; jp < 4; ++jp) {
            float x, y;
            upk2(acc[i][jp], x, y);
            best = fmaxf(best, x * inv[2 * jp]);
            best = fmaxf(best, y * inv[2 * jp + 1]);
        }
        m[i] = best;
    }
#pragma unroll
    for (int o = 8; o; o >>= 1)
#pragma unroll
        for (int i = 0; i < 4; ++i)
            m[i] = fmaxf(m[i], __shfl_xor_sync(0xffffffffu, m[i], o));

    if (tx == 0) {
#pragma unroll
        for (int i = 0; i < 4; ++i)
            g_partmax[(qbase + ty + 16 * i) * 32 + blockIdx.x] = m[i];
    }
}

// ---------------------------------------------------------------------------
// D: one block per query. Warp0 combines partial maxes; warps 1-7 do the 7
// negatives in parallel; thread 0 computes CE.
// ---------------------------------------------------------------------------
__global__ void finalize_kernel(const float* __restrict__ negs) {
    int q = blockIdx.x;
    int warp = threadIdx.x >> 5, lane = threadIdx.x & 31;
    __shared__ float slog[8];

    if (warp == 0) {
        float pm = g_partmax[q * 32 + lane];
#pragma unroll
        for (int o = 16; o; o >>= 1) pm = fmaxf(pm, __shfl_xor_sync(0xffffffffu, pm, o));
        if (lane == 0) slog[0] = pm * INV_TAU;
    } else {
        int n = warp - 1;
        float4 qv = *reinterpret_cast<const float4*>(&g_q[q * Cv + lane * 4]);
        float4 nv = *reinterpret_cast<const float4*>(
            &negs[((size_t)q * NNEG + n) * Cv + lane * 4]);
        float d  = nv.x * qv.x + nv.y * qv.y + nv.z * qv.z + nv.w * qv.w;
        float s2 = nv.x * nv.x + nv.y * nv.y + nv.z * nv.z + nv.w * nv.w;
#pragma unroll
        for (int o = 16; o; o >>= 1) {
            d  += __shfl_xor_sync(0xffffffffu, d, o);
            s2 += __shfl_xor_sync(0xffffffffu, s2, o);
        }
        if (lane == 0) slog[1 + n] = d / fmaxf(sqrtf(s2), 1e-12f) * INV_TAU;
    }
    __syncthreads();
    if (threadIdx.x == 0) {
        float mx = slog[0];
#pragma unroll
        for (int i = 1; i < 8; ++i) mx = fmaxf(mx, slog[i]);
        float se = 0.0f;
#pragma unroll
        for (int i = 0; i < 8; ++i) se += expf(slog[i] - mx);
        g_loss[q] = -(slog[0] - mx - logf(se));
    }
}

// ---------------------------------------------------------------------------
// E: deterministic mean of 512 losses
// ---------------------------------------------------------------------------
__global__ void reduce_kernel(float* __restrict__ out) {
    __shared__ float red[256];
    int t = threadIdx.x;
    red[t] = g_loss[t] + g_loss[t + 256];
    __syncthreads();
    for (int s = 128; s; s >>= 1) {
        if (t < s) red[t] += red[t + s];
        __syncthreads();
    }
    if (t == 0) out[0] = red[0] * (1.0f / (float)BKv);
}

// ---------------------------------------------------------------------------
extern "C" void kernel_launch(void* const* d_in, const int* in_sizes, int n_in,
                              void* d_out, int out_size) {
    const float* feat = (const float*)d_in[0];
    const float* pool = (const float*)d_in[1];
    const float* negs = (const float*)d_in[2];
    const int*   qidx = (const int*)d_in[3];
    float* out = (float*)d_out;

    cudaFuncSetAttribute(sim_kernel,
                         cudaFuncAttributeMaxDynamicSharedMemorySize,
                         SIM_SMEM_BYTES);

    prep_kernel<<<1024, 256>>>(pool, feat, qidx);
    sim_kernel<<<dim3(32, 8), 256, SIM_SMEM_BYTES>>>(pool);
    finalize_kernel<<<BKv, 256>>>(negs);
    reduce_kernel<<<1, 256>>>(out);
}